// round 5
// baseline (speedup 1.0000x reference)
#include <cuda_runtime.h>
#include <math.h>

// Retention: B=8, S=2048, D=128, gamma=0.9865.
// out[n] = a[n]/sqrt(d) * ( Q'[n] @ Mbase[chunk(n)] + intra-chunk causal (Q'.xk)*c @ V )
//   a[n]=g^-n, b[m]=g^m/sqrt(r[m]), r[m]=sum_{t<=m} g^-t
//   Q' = xq @ (W W^T), V = xv @ W, K = raw xk   (QK^T = xq (W W^T) xk^T)
//   s[n] = a[n]/sqrt(d) * Q'[n].P[n], P = prefix of b[m]*xk[m]; c[m]=b[m]/max(|s[m]|,1)
//   U[ch] = sum_{m in ch} c[m] xk[m] (x) V[m]; Mbase = exclusive chunk prefix of U

#define SB 8
#define SS 2048
#define SD 128
#define NCH 16
#define CH 128

__device__ float g_a[SS];
__device__ float g_b[SS];
__device__ float g_G[SD * SD];
__device__ float g_Qp[SB * SS * SD];
__device__ float g_Vp[SB * SS * SD];
__device__ float g_Tk[SB * NCH * SD];
__device__ float g_Pb[SB * NCH * SD];
__device__ float g_s[SB * SS];
__device__ float g_U[SB * NCH * SD * SD];
__device__ float g_Mb[SB * NCH * SD * SD];

__device__ __forceinline__ float inv_sqrt_d() { return 0.08838834764831843f; }

// ---------------------------------------------------------------- K0: G = W W^T  (+ decay coeffs)
// grid 16 x 256; block computes 8 rows of G and 128 coeff entries. dyn smem 128*129*4.
__global__ void k_gram(const float* __restrict__ W) {
    extern __shared__ float Ws[];  // [128][129]
    int tid = threadIdx.x;
    if (tid < 128) {
        int n = blockIdx.x * 128 + tid;
        const double g = 0.9865;
        const double ig = 1.0 / g;
        double r = (pow(ig, (double)(n + 1)) - 1.0) / (ig - 1.0);  // sum_{t=0}^{n} ig^t
        g_a[n] = (float)pow(ig, (double)n);
        g_b[n] = (float)(pow(g, (double)n) / sqrt(r));
    }
    for (int i = tid; i < SD * SD; i += 256) {
        int r = i >> 7, c = i & 127;
        Ws[r * 129 + c] = W[i];
    }
    __syncthreads();
    int j = tid & 127;
    int ir = tid >> 7;  // 0..1
    int i0 = blockIdx.x * 8;
#pragma unroll
    for (int rr = 0; rr < 4; rr++) {
        int i = i0 + ir + 2 * rr;
        float acc = 0.f;
#pragma unroll 8
        for (int t = 0; t < SD; t++) acc += Ws[i * 129 + t] * Ws[j * 129 + t];
        g_G[i * SD + j] = acc;
    }
}

// ---------------------------------------------------------------- K1: projections
// grid (128, 2): job 0: Qp = xq @ G ; job 1: Vp = xv @ W.  dyn smem 2*16384*4.
__global__ void __launch_bounds__(256) k_proj(const float* __restrict__ xq,
                                              const float* __restrict__ xv,
                                              const float* __restrict__ W) {
    extern __shared__ float sm[];
    float* As = sm;              // [128][128]
    float* Bs = sm + SD * SD;    // [128][128]
    int job = blockIdx.y;
    const float* X = job ? xv : xq;
    const float* Wm = job ? W : g_G;
    float* Y = job ? g_Vp : g_Qp;
    size_t row0 = (size_t)blockIdx.x * 128;
    int tid = threadIdx.x;
    {
        const float4* Xv = (const float4*)(X + row0 * SD);
        const float4* Wv = (const float4*)Wm;
        float4* Av = (float4*)As;
        float4* Bv = (float4*)Bs;
        for (int i = tid; i < SD * SD / 4; i += 256) { Av[i] = Xv[i]; Bv[i] = Wv[i]; }
    }
    __syncthreads();
    int ty = tid >> 4, tx = tid & 15;
    float acc[8][8];
#pragma unroll
    for (int ii = 0; ii < 8; ii++)
#pragma unroll
        for (int jj = 0; jj < 8; jj++) acc[ii][jj] = 0.f;
#pragma unroll 4
    for (int k = 0; k < SD; k++) {
        float a8[8], b8[8];
#pragma unroll
        for (int ii = 0; ii < 8; ii++) a8[ii] = As[((ty + (ii << 4)) << 7) + k];
#pragma unroll
        for (int jj = 0; jj < 8; jj++) b8[jj] = Bs[(k << 7) + tx + (jj << 4)];
#pragma unroll
        for (int ii = 0; ii < 8; ii++)
#pragma unroll
            for (int jj = 0; jj < 8; jj++) acc[ii][jj] += a8[ii] * b8[jj];
    }
#pragma unroll
    for (int ii = 0; ii < 8; ii++) {
        int n = ty + (ii << 4);
#pragma unroll
        for (int jj = 0; jj < 8; jj++)
            Y[(row0 + n) * SD + tx + (jj << 4)] = acc[ii][jj];
    }
}

// ---------------------------------------------------------------- K2: per-chunk sums of b[m]*xk[m]
__global__ void k_chunksum(const float* __restrict__ xk) {
    int b = blockIdx.y, ch = blockIdx.x, d = threadIdx.x;
    int m0 = ch * CH;
    const float* base = xk + ((size_t)b * SS + m0) * SD;
    float acc = 0.f;
#pragma unroll 4
    for (int m = 0; m < CH; m++) acc += g_b[m0 + m] * base[m * SD + d];
    g_Tk[((size_t)b * NCH + ch) * SD + d] = acc;
}

// ---------------------------------------------------------------- K3: exclusive prefix over chunks (vector)
__global__ void k_prefix_vec() {
    int b = blockIdx.x, d = threadIdx.x;
    float run = 0.f;
    for (int ch = 0; ch < NCH; ch++) {
        size_t o = ((size_t)b * NCH + ch) * SD + d;
        g_Pb[o] = run;
        run += g_Tk[o];
    }
}

// ---------------------------------------------------------------- K4: fused s + U per chunk
// grid (16, 8) x 256 thr. dyn smem: Kraw[128*129] + Pt[128*129] + Vs[128*128] + cs[128]
__global__ void __launch_bounds__(256) k_su(const float* __restrict__ xk) {
    extern __shared__ float sm[];
    float* Kraw = sm;                         // [128][129] raw xk chunk
    float* Pt = sm + 16512;                   // [128][129] b-weighted prefix
    float* Vs = sm + 2 * 16512;               // [128][128] V (later c-scaled)
    float* cs = sm + 2 * 16512 + SD * SD;     // [128]
    int b = blockIdx.y, ch = blockIdx.x, tid = threadIdx.x;
    int m0 = ch * CH;
    const float* kb = xk + ((size_t)b * SS + m0) * SD;
    const float* vb = g_Vp + ((size_t)b * SS + m0) * SD;
    for (int i = tid; i < SD * SD; i += 256) {
        int m = i >> 7, t = i & 127;
        float kv = kb[i];
        Kraw[m * 129 + t] = kv;
        Pt[m * 129 + t] = g_b[m0 + m] * kv;
        Vs[i] = vb[i];
    }
    __syncthreads();
    // inclusive prefix along m, per dim-column t (threads 0..127)
    if (tid < 128) {
        int t = tid;
        float run = g_Pb[((size_t)b * NCH + ch) * SD + t];
#pragma unroll 4
        for (int m = 0; m < CH; m++) {
            run += Pt[m * 129 + t];
            Pt[m * 129 + t] = run;
        }
    }
    __syncthreads();
    // s[t] = a/sqrt(d) * Q'[t] . Pt[t][:]; c[t] = b/max(|s|,1)
    if (tid < 128) {
        int t = tid;
        const float* qrow = g_Qp + ((size_t)b * SS + m0 + t) * SD;
        float acc = 0.f;
#pragma unroll 4
        for (int d = 0; d < SD; d++) acc += qrow[d] * Pt[t * 129 + d];
        float sv = g_a[m0 + t] * inv_sqrt_d() * acc;
        g_s[b * SS + m0 + t] = sv;
        cs[t] = g_b[m0 + t] / fmaxf(fabsf(sv), 1.0f);
    }
    __syncthreads();
    // fold c into V rows once (cheaper than per-FMA scaling)
    for (int i = tid; i < SD * SD; i += 256) Vs[i] *= cs[i >> 7];
    __syncthreads();
    // U[i][j] = sum_m Kraw[m][i] * Vs[m][j]
    int ty = tid >> 4, tx = tid & 15;
    float acc[8][8];
#pragma unroll
    for (int ii = 0; ii < 8; ii++)
#pragma unroll
        for (int jj = 0; jj < 8; jj++) acc[ii][jj] = 0.f;
#pragma unroll 4
    for (int m = 0; m < CH; m++) {
        float a8[8], b8[8];
#pragma unroll
        for (int ii = 0; ii < 8; ii++) a8[ii] = Kraw[m * 129 + ty + (ii << 4)];
#pragma unroll
        for (int jj = 0; jj < 8; jj++) b8[jj] = Vs[(m << 7) + tx + (jj << 4)];
#pragma unroll
        for (int ii = 0; ii < 8; ii++)
#pragma unroll
            for (int jj = 0; jj < 8; jj++) acc[ii][jj] += a8[ii] * b8[jj];
    }
    float* ub = g_U + (((size_t)b * NCH + ch) << 14);
#pragma unroll
    for (int ii = 0; ii < 8; ii++)
#pragma unroll
        for (int jj = 0; jj < 8; jj++)
            ub[(ty + (ii << 4)) * SD + tx + (jj << 4)] = acc[ii][jj];
}

// ---------------------------------------------------------------- K5: exclusive prefix over chunks (matrix)
__global__ void k_prefix_mat() {
    int idx = blockIdx.x * 256 + threadIdx.x;  // over SB * 16384
    int b = idx >> 14;
    int e = idx & 16383;
    float run = 0.f;
    for (int ch = 0; ch < NCH; ch++) {
        size_t o = (((size_t)b * NCH + ch) << 14) + e;
        g_Mb[o] = run;
        run += g_U[o];
    }
}

// ---------------------------------------------------------------- K6: output
// grid (16, 8) x 256 thr, dyn smem (16384 + 16512 + 16512)*4 = 197632 B.
__global__ void __launch_bounds__(256) k_out(const float* __restrict__ xk,
                                             float* __restrict__ out) {
    extern __shared__ float sm[];
    float* Qs = sm;                        // [128][128]  later reused for V
    float* Ks = sm + 16384;                // [128][129]  later reused for Mbase
    float* Ss = sm + 16384 + 16512;        // [128][129]
    int b = blockIdx.y, ch = blockIdx.x, tid = threadIdx.x;
    int n0 = ch * CH;
    const float* qb = g_Qp + ((size_t)b * SS + n0) * SD;
    const float* kb = xk + ((size_t)b * SS + n0) * SD;
    for (int i = tid; i < SD * SD; i += 256) {
        int r = i >> 7, c = i & 127;
        Qs[i] = qb[i];
        Ks[r * 129 + c] = kb[i];
    }
    int ty = tid >> 4, tx = tid & 15;
    float cj[8];
#pragma unroll
    for (int jj = 0; jj < 8; jj++) {
        int ml = tx + (jj << 4);
        float sv = g_s[b * SS + n0 + ml];
        cj[jj] = g_b[n0 + ml] / fmaxf(fabsf(sv), 1.0f);
    }
    __syncthreads();

    // ---- phase 1: S = (Q' . K^T) masked * c  (NT gemm)
    {
        float acc[8][8];
#pragma unroll
        for (int ii = 0; ii < 8; ii++)
#pragma unroll
            for (int jj = 0; jj < 8; jj++) acc[ii][jj] = 0.f;
#pragma unroll 4
        for (int k = 0; k < SD; k++) {
            float a8[8], b8[8];
#pragma unroll
            for (int ii = 0; ii < 8; ii++) a8[ii] = Qs[((ty + (ii << 4)) << 7) + k];
#pragma unroll
            for (int jj = 0; jj < 8; jj++) b8[jj] = Ks[(tx + (jj << 4)) * 129 + k];
#pragma unroll
            for (int ii = 0; ii < 8; ii++)
#pragma unroll
                for (int jj = 0; jj < 8; jj++) acc[ii][jj] += a8[ii] * b8[jj];
        }
#pragma unroll
        for (int ii = 0; ii < 8; ii++) {
            int nl = ty + (ii << 4);
#pragma unroll
            for (int jj = 0; jj < 8; jj++) {
                int ml = tx + (jj << 4);
                Ss[nl * 129 + ml] = (ml <= nl) ? acc[ii][jj] * cj[jj] : 0.f;
            }
        }
    }
    __syncthreads();

    // ---- phase 2a: load Mbase into Ks slot; o = Q' @ Mbase (NN)
    {
        const float* mb = g_Mb + (((size_t)b * NCH + ch) << 14);
        for (int i = tid; i < SD * SD; i += 256) {
            int r = i >> 7, c = i & 127;
            Ks[r * 129 + c] = mb[i];
        }
    }
    __syncthreads();
    float o8[8][8];
#pragma unroll
    for (int ii = 0; ii < 8; ii++)
#pragma unroll
        for (int jj = 0; jj < 8; jj++) o8[ii][jj] = 0.f;
#pragma unroll 4
    for (int k = 0; k < SD; k++) {
        float a8[8], b8[8];
#pragma unroll
        for (int ii = 0; ii < 8; ii++) a8[ii] = Qs[((ty + (ii << 4)) << 7) + k];
#pragma unroll
        for (int jj = 0; jj < 8; jj++) b8[jj] = Ks[k * 129 + tx + (jj << 4)];
#pragma unroll
        for (int ii = 0; ii < 8; ii++)
#pragma unroll
            for (int jj = 0; jj < 8; jj++) o8[ii][jj] += a8[ii] * b8[jj];
    }
    __syncthreads();

    // ---- phase 2b: load V into Qs slot; o += Ss @ V (NN)
    {
        const float* vb = g_Vp + ((size_t)b * SS + n0) * SD;
        for (int i = tid; i < SD * SD; i += 256) Qs[i] = vb[i];
    }
    __syncthreads();
#pragma unroll 4
    for (int k = 0; k < CH; k++) {
        float a8[8], b8[8];
#pragma unroll
        for (int ii = 0; ii < 8; ii++) a8[ii] = Ss[(ty + (ii << 4)) * 129 + k];
#pragma unroll
        for (int jj = 0; jj < 8; jj++) b8[jj] = Qs[(k << 7) + tx + (jj << 4)];
#pragma unroll
        for (int ii = 0; ii < 8; ii++)
#pragma unroll
            for (int jj = 0; jj < 8; jj++) o8[ii][jj] += a8[ii] * b8[jj];
    }

    // ---- scale by a[n]/sqrt(d) and store
    float* ob = out + ((size_t)b * SS + n0) * SD;
#pragma unroll
    for (int ii = 0; ii < 8; ii++) {
        int nl = ty + (ii << 4);
        float rs = g_a[n0 + nl] * inv_sqrt_d();
#pragma unroll
        for (int jj = 0; jj < 8; jj++)
            ob[nl * SD + tx + (jj << 4)] = o8[ii][jj] * rs;
    }
}

// ---------------------------------------------------------------- launch
extern "C" void kernel_launch(void* const* d_in, const int* in_sizes, int n_in,
                              void* d_out, int out_size) {
    const float* W = nullptr;
    const float* big[3] = {nullptr, nullptr, nullptr};
    int nb = 0;
    for (int i = 0; i < n_in; i++) {
        if (in_sizes[i] == SD * SD) W = (const float*)d_in[i];
        else if (nb < 3) big[nb++] = (const float*)d_in[i];
    }
    const float* xq = big[0];
    const float* xk = big[1];
    const float* xv = big[2];
    float* out = (float*)d_out;

    cudaFuncSetAttribute(k_gram, cudaFuncAttributeMaxDynamicSharedMemorySize, 66048);
    cudaFuncSetAttribute(k_proj, cudaFuncAttributeMaxDynamicSharedMemorySize, 131072);
    cudaFuncSetAttribute(k_su, cudaFuncAttributeMaxDynamicSharedMemorySize, 198144);
    cudaFuncSetAttribute(k_out, cudaFuncAttributeMaxDynamicSharedMemorySize, 197632);

    k_gram<<<16, 256, 66048>>>(W);
    k_proj<<<dim3(SB * SS / 128, 2), 256, 131072>>>(xq, xv, W);
    k_chunksum<<<dim3(NCH, SB), 128>>>(xk);
    k_prefix_vec<<<SB, 128>>>();
    k_su<<<dim3(NCH, SB), 256, 198144>>>(xk);
    k_prefix_mat<<<SB * SD * SD / 256, 256>>>();
    k_out<<<dim3(NCH, SB), 256, 197632>>>(xk, out);
}

// round 17
// speedup vs baseline: 1.1250x; 1.1250x over previous
#include <cuda_runtime.h>
#include <math.h>

// Retention: B=8, S=2048, D=128, gamma=0.9865.
// out[n] = a[n]/sqrt(d) * ( Q'[n] @ Mbase[chunk(n)] + intra-chunk causal (Q'.xk)*c @ V )
//   a[n]=g^-n, b[m]=g^m/sqrt(r[m]), r[m]=sum_{t<=m} g^-t
//   Q' = xq @ (W W^T), V = xv @ W, K = raw xk   (QK^T = xq (W W^T) xk^T)
//   s[n] = a[n]/sqrt(d) * Q'[n].P[n], P = prefix of b[m]*xk[m]; c[m]=b[m]/max(|s[m]|,1)
//   U[ch] = sum_{m in ch} c[m] xk[m] (x) V[m]; Mbase = exclusive chunk prefix of U
//
// vs 166.4us baseline: (a) serial-LDG prefix kernels removed (prefix base folded
// into k_su; k_prefix_mat loads all 16 upfront, MLP=16);
// (b) GEMM microkernels use packed fma.rn.f32x2 (FFMA2) -> 2 lane-FMA/instr.

#define SB 8
#define SS 2048
#define SD 128
#define NCH 16
#define CH 128

__device__ float g_a[SS];
__device__ float g_b[SS];
__device__ float g_G[SD * SD];
__device__ float g_Qp[SB * SS * SD];
__device__ float g_Vp[SB * SS * SD];
__device__ float g_Tk[SB * NCH * SD];
__device__ float g_s[SB * SS];
__device__ float g_U[SB * NCH * SD * SD];
__device__ float g_Mb[SB * NCH * SD * SD];

__device__ __forceinline__ float inv_sqrt_d() { return 0.08838834764831843f; }

// ---- packed f32x2 helpers (Blackwell FFMA2 path; PTX-only per SASS_QUICKREF)
__device__ __forceinline__ unsigned long long pk2(float lo, float hi) {
    unsigned long long r;
    asm("mov.b64 %0, {%1, %2};" : "=l"(r) : "f"(lo), "f"(hi));
    return r;
}
__device__ __forceinline__ void upk2(unsigned long long v, float& lo, float& hi) {
    asm("mov.b64 {%0, %1}, %2;" : "=f"(lo), "=f"(hi) : "l"(v));
}
__device__ __forceinline__ void fma2(unsigned long long& d, unsigned long long a,
                                     unsigned long long b) {
    asm("fma.rn.f32x2 %0, %1, %2, %0;" : "+l"(d) : "l"(a), "l"(b));
}

// ---------------------------------------------------------------- K0: G = W W^T  (+ decay coeffs)
__global__ void k_gram(const float* __restrict__ W) {
    extern __shared__ float Ws[];  // [128][129]
    int tid = threadIdx.x;
    if (tid < 128) {
        int n = blockIdx.x * 128 + tid;
        const double g = 0.9865;
        const double ig = 1.0 / g;
        double r = (pow(ig, (double)(n + 1)) - 1.0) / (ig - 1.0);
        g_a[n] = (float)pow(ig, (double)n);
        g_b[n] = (float)(pow(g, (double)n) / sqrt(r));
    }
    for (int i = tid; i < SD * SD; i += 256) {
        int r = i >> 7, c = i & 127;
        Ws[r * 129 + c] = W[i];
    }
    __syncthreads();
    int j = tid & 127;
    int ir = tid >> 7;
    int i0 = blockIdx.x * 8;
#pragma unroll
    for (int rr = 0; rr < 4; rr++) {
        int i = i0 + ir + 2 * rr;
        float acc = 0.f;
#pragma unroll 8
        for (int t = 0; t < SD; t++) acc += Ws[i * 129 + t] * Ws[j * 129 + t];
        g_G[i * SD + j] = acc;
    }
}

// ---------------------------------------------------------------- K1: projections (FFMA2)
// grid (128, 2): job 0: Qp = xq @ G ; job 1: Vp = xv @ W.
__global__ void __launch_bounds__(256) k_proj(const float* __restrict__ xq,
                                              const float* __restrict__ xv,
                                              const float* __restrict__ W) {
    extern __shared__ float sm[];
    float* As = sm;              // [128][128]
    float* Bs = sm + SD * SD;    // [128][128]
    int job = blockIdx.y;
    const float* X = job ? xv : xq;
    const float* Wm = job ? W : g_G;
    float* Y = job ? g_Vp : g_Qp;
    size_t row0 = (size_t)blockIdx.x * 128;
    int tid = threadIdx.x;
    {
        const float4* Xv = (const float4*)(X + row0 * SD);
        const float4* Wv = (const float4*)Wm;
        float4* Av = (float4*)As;
        float4* Bv = (float4*)Bs;
        for (int i = tid; i < SD * SD / 4; i += 256) { Av[i] = Xv[i]; Bv[i] = Wv[i]; }
    }
    __syncthreads();
    int ty = tid >> 4, tx = tid & 15;
    unsigned long long acc2[8][4];
#pragma unroll
    for (int ii = 0; ii < 8; ii++)
#pragma unroll
        for (int j4 = 0; j4 < 4; j4++) acc2[ii][j4] = 0ull;
#pragma unroll 4
    for (int k = 0; k < SD; k++) {
        float a8[8];
        unsigned long long b2[4];
#pragma unroll
        for (int ii = 0; ii < 8; ii++) a8[ii] = As[((ty + (ii << 4)) << 7) + k];
#pragma unroll
        for (int j4 = 0; j4 < 4; j4++)
            b2[j4] = pk2(Bs[(k << 7) + tx + (j4 << 5)], Bs[(k << 7) + tx + (j4 << 5) + 16]);
#pragma unroll
        for (int ii = 0; ii < 8; ii++) {
            unsigned long long a2 = pk2(a8[ii], a8[ii]);
#pragma unroll
            for (int j4 = 0; j4 < 4; j4++) fma2(acc2[ii][j4], a2, b2[j4]);
        }
    }
#pragma unroll
    for (int ii = 0; ii < 8; ii++) {
        int n = ty + (ii << 4);
#pragma unroll
        for (int j4 = 0; j4 < 4; j4++) {
            float lo, hi;
            upk2(acc2[ii][j4], lo, hi);
            Y[(row0 + n) * SD + tx + (j4 << 5)] = lo;
            Y[(row0 + n) * SD + tx + (j4 << 5) + 16] = hi;
        }
    }
}

// ---------------------------------------------------------------- K2: per-chunk sums of b[m]*xk[m]
__global__ void k_chunksum(const float* __restrict__ xk) {
    int b = blockIdx.y, ch = blockIdx.x, d = threadIdx.x;
    int m0 = ch * CH;
    const float* base = xk + ((size_t)b * SS + m0) * SD;
    float acc = 0.f;
#pragma unroll 4
    for (int m = 0; m < CH; m++) acc += g_b[m0 + m] * base[m * SD + d];
    g_Tk[((size_t)b * NCH + ch) * SD + d] = acc;
}

// ---------------------------------------------------------------- K3: fused s + U per chunk (FFMA2)
// grid (16, 8) x 256 thr. Computes its own prefix base from g_Tk (<=15 indep loads).
__global__ void __launch_bounds__(256) k_su(const float* __restrict__ xk) {
    extern __shared__ float sm[];
    float* Kraw = sm;                         // [128][129]
    float* Pt = sm + 16512;                   // [128][129]
    float* Vs = sm + 2 * 16512;               // [128][128]
    float* cs = sm + 2 * 16512 + SD * SD;     // [128]
    int b = blockIdx.y, ch = blockIdx.x, tid = threadIdx.x;
    int m0 = ch * CH;
    const float* kb = xk + ((size_t)b * SS + m0) * SD;
    const float* vb = g_Vp + ((size_t)b * SS + m0) * SD;
    for (int i = tid; i < SD * SD; i += 256) {
        int m = i >> 7, t = i & 127;
        float kv = kb[i];
        Kraw[m * 129 + t] = kv;
        Pt[m * 129 + t] = g_b[m0 + m] * kv;
        Vs[i] = vb[i];
    }
    __syncthreads();
    if (tid < 128) {
        int t = tid;
        // exclusive chunk-prefix base: independent loads, summed locally
        float run = 0.f;
        for (int c = 0; c < ch; c++) run += g_Tk[((size_t)b * NCH + c) * SD + t];
#pragma unroll 4
        for (int m = 0; m < CH; m++) {
            run += Pt[m * 129 + t];
            Pt[m * 129 + t] = run;
        }
    }
    __syncthreads();
    if (tid < 128) {
        int t = tid;
        const float* qrow = g_Qp + ((size_t)b * SS + m0 + t) * SD;
        float acc = 0.f;
#pragma unroll 4
        for (int d = 0; d < SD; d++) acc += qrow[d] * Pt[t * 129 + d];
        float sv = g_a[m0 + t] * inv_sqrt_d() * acc;
        g_s[b * SS + m0 + t] = sv;
        cs[t] = g_b[m0 + t] / fmaxf(fabsf(sv), 1.0f);
    }
    __syncthreads();
    for (int i = tid; i < SD * SD; i += 256) Vs[i] *= cs[i >> 7];
    __syncthreads();
    // U[i][j] = sum_m Kraw[m][i] * Vs[m][j]
    int ty = tid >> 4, tx = tid & 15;
    unsigned long long acc2[8][4];
#pragma unroll
    for (int ii = 0; ii < 8; ii++)
#pragma unroll
        for (int j4 = 0; j4 < 4; j4++) acc2[ii][j4] = 0ull;
#pragma unroll 4
    for (int m = 0; m < CH; m++) {
        float a8[8];
        unsigned long long b2[4];
#pragma unroll
        for (int ii = 0; ii < 8; ii++) a8[ii] = Kraw[m * 129 + ty + (ii << 4)];
#pragma unroll
        for (int j4 = 0; j4 < 4; j4++)
            b2[j4] = pk2(Vs[(m << 7) + tx + (j4 << 5)], Vs[(m << 7) + tx + (j4 << 5) + 16]);
#pragma unroll
        for (int ii = 0; ii < 8; ii++) {
            unsigned long long a2 = pk2(a8[ii], a8[ii]);
#pragma unroll
            for (int j4 = 0; j4 < 4; j4++) fma2(acc2[ii][j4], a2, b2[j4]);
        }
    }
    float* ub = g_U + (((size_t)b * NCH + ch) << 14);
#pragma unroll
    for (int ii = 0; ii < 8; ii++)
#pragma unroll
        for (int j4 = 0; j4 < 4; j4++) {
            float lo, hi;
            upk2(acc2[ii][j4], lo, hi);
            ub[(ty + (ii << 4)) * SD + tx + (j4 << 5)] = lo;
            ub[(ty + (ii << 4)) * SD + tx + (j4 << 5) + 16] = hi;
        }
}

// ---------------------------------------------------------------- K4: exclusive prefix over chunks (matrix)
// Load all 16 upfront (MLP=16), prefix in registers, store 16.
__global__ void k_prefix_mat() {
    int idx = blockIdx.x * 256 + threadIdx.x;  // over SB * 16384
    int b = idx >> 14;
    int e = idx & 16383;
    size_t base = ((size_t)b * NCH << 14) + e;
    float v[NCH];
#pragma unroll
    for (int ch = 0; ch < NCH; ch++) v[ch] = g_U[base + ((size_t)ch << 14)];
    float run = 0.f;
#pragma unroll
    for (int ch = 0; ch < NCH; ch++) {
        g_Mb[base + ((size_t)ch << 14)] = run;
        run += v[ch];
    }
}

// ---------------------------------------------------------------- K5: output (FFMA2)
__global__ void __launch_bounds__(256) k_out(const float* __restrict__ xk,
                                             float* __restrict__ out) {
    extern __shared__ float sm[];
    float* Qs = sm;                        // [128][128]  later reused for V
    float* Ks = sm + 16384;                // [128][129]  later reused for Mbase
    float* Ss = sm + 16384 + 16512;        // [128][129]
    int b = blockIdx.y, ch = blockIdx.x, tid = threadIdx.x;
    int n0 = ch * CH;
    const float* qb = g_Qp + ((size_t)b * SS + n0) * SD;
    const float* kb = xk + ((size_t)b * SS + n0) * SD;
    for (int i = tid; i < SD * SD; i += 256) {
        int r = i >> 7, c = i & 127;
        Qs[i] = qb[i];
        Ks[r * 129 + c] = kb[i];
    }
    int ty = tid >> 4, tx = tid & 15;
    // per-thread column factors c[m] for columns tx + j4*32 (+16)
    float clo[4], chi[4];
#pragma unroll
    for (int j4 = 0; j4 < 4; j4++) {
        int m1 = tx + (j4 << 5), m2 = m1 + 16;
        float s1 = g_s[b * SS + n0 + m1], s2 = g_s[b * SS + n0 + m2];
        clo[j4] = g_b[n0 + m1] / fmaxf(fabsf(s1), 1.0f);
        chi[j4] = g_b[n0 + m2] / fmaxf(fabsf(s2), 1.0f);
    }
    __syncthreads();

    // ---- phase 1: S = (Q' . K^T) masked * c  (NT gemm, FFMA2)
    {
        unsigned long long acc2[8][4];
#pragma unroll
        for (int ii = 0; ii < 8; ii++)
#pragma unroll
            for (int j4 = 0; j4 < 4; j4++) acc2[ii][j4] = 0ull;
#pragma unroll 4
        for (int k = 0; k < SD; k++) {
            float a8[8];
            unsigned long long b2[4];
#pragma unroll
            for (int ii = 0; ii < 8; ii++) a8[ii] = Qs[((ty + (ii << 4)) << 7) + k];
#pragma unroll
            for (int j4 = 0; j4 < 4; j4++)
                b2[j4] = pk2(Ks[(tx + (j4 << 5)) * 129 + k], Ks[(tx + (j4 << 5) + 16) * 129 + k]);
#pragma unroll
            for (int ii = 0; ii < 8; ii++) {
                unsigned long long a2 = pk2(a8[ii], a8[ii]);
#pragma unroll
                for (int j4 = 0; j4 < 4; j4++) fma2(acc2[ii][j4], a2, b2[j4]);
            }
        }
#pragma unroll
        for (int ii = 0; ii < 8; ii++) {
            int nl = ty + (ii << 4);
#pragma unroll
            for (int j4 = 0; j4 < 4; j4++) {
                float lo, hi;
                upk2(acc2[ii][j4], lo, hi);
                int m1 = tx + (j4 << 5), m2 = m1 + 16;
                Ss[nl * 129 + m1] = (m1 <= nl) ? lo * clo[j4] : 0.f;
                Ss[nl * 129 + m2] = (m2 <= nl) ? hi * chi[j4] : 0.f;
            }
        }
    }
    __syncthreads();

    // ---- phase 2a: load Mbase into Ks slot; o = Q' @ Mbase (NN, FFMA2)
    {
        const float* mb = g_Mb + (((size_t)b * NCH + ch) << 14);
        for (int i = tid; i < SD * SD; i += 256) {
            int r = i >> 7, c = i & 127;
            Ks[r * 129 + c] = mb[i];
        }
    }
    __syncthreads();
    unsigned long long o2[8][4];
#pragma unroll
    for (int ii = 0; ii < 8; ii++)
#pragma unroll
        for (int j4 = 0; j4 < 4; j4++) o2[ii][j4] = 0ull;
#pragma unroll 4
    for (int k = 0; k < SD; k++) {
        float a8[8];
        unsigned long long b2[4];
#pragma unroll
        for (int ii = 0; ii < 8; ii++) a8[ii] = Qs[((ty + (ii << 4)) << 7) + k];
#pragma unroll
        for (int j4 = 0; j4 < 4; j4++)
            b2[j4] = pk2(Ks[k * 129 + tx + (j4 << 5)], Ks[k * 129 + tx + (j4 << 5) + 16]);
#pragma unroll
        for (int ii = 0; ii < 8; ii++) {
            unsigned long long a2 = pk2(a8[ii], a8[ii]);
#pragma unroll
            for (int j4 = 0; j4 < 4; j4++) fma2(o2[ii][j4], a2, b2[j4]);
        }
    }
    __syncthreads();

    // ---- phase 2b: load V into Qs slot; o += Ss @ V (NN, FFMA2)
    {
        const float* vb = g_Vp + ((size_t)b * SS + n0) * SD;
        for (int i = tid; i < SD * SD; i += 256) Qs[i] = vb[i];
    }
    __syncthreads();
#pragma unroll 4
    for (int k = 0; k < CH; k++) {
        float a8[8];
        unsigned long long b2[4];
#pragma unroll
        for (int ii = 0; ii < 8; ii++) a8[ii] = Ss[(ty + (ii << 4)) * 129 + k];
#pragma unroll
        for (int j4 = 0; j4 < 4; j4++)
            b2[j4] = pk2(Qs[(k << 7) + tx + (j4 << 5)], Qs[(k << 7) + tx + (j4 << 5) + 16]);
#pragma unroll
        for (int ii = 0; ii < 8; ii++) {
            unsigned long long a2 = pk2(a8[ii], a8[ii]);
#pragma unroll
            for (int j4 = 0; j4 < 4; j4++) fma2(o2[ii][j4], a2, b2[j4]);
        }
    }

    // ---- scale by a[n]/sqrt(d) and store
    float* ob = out + ((size_t)b * SS + n0) * SD;
#pragma unroll
    for (int ii = 0; ii < 8; ii++) {
        int nl = ty + (ii << 4);
        float rs = g_a[n0 + nl] * inv_sqrt_d();
#pragma unroll
        for (int j4 = 0; j4 < 4; j4++) {
            float lo, hi;
            upk2(o2[ii][j4], lo, hi);
            ob[nl * SD + tx + (j4 << 5)] = lo * rs;
            ob[nl * SD + tx + (j4 << 5) + 16] = hi * rs;
        }
    }
}

// ---------------------------------------------------------------- launch
extern "C" void kernel_launch(void* const* d_in, const int* in_sizes, int n_in,
                              void* d_out, int out_size) {
    const float* W = nullptr;
    const float* big[3] = {nullptr, nullptr, nullptr};
    int nb = 0;
    for (int i = 0; i < n_in; i++) {
        if (in_sizes[i] == SD * SD) W = (const float*)d_in[i];
        else if (nb < 3) big[nb++] = (const float*)d_in[i];
    }
    const float* xq = big[0];
    const float* xk = big[1];
    const float* xv = big[2];
    float* out = (float*)d_out;

    cudaFuncSetAttribute(k_gram, cudaFuncAttributeMaxDynamicSharedMemorySize, 66048);
    cudaFuncSetAttribute(k_proj, cudaFuncAttributeMaxDynamicSharedMemorySize, 131072);
    cudaFuncSetAttribute(k_su, cudaFuncAttributeMaxDynamicSharedMemorySize, 198144);
    cudaFuncSetAttribute(k_out, cudaFuncAttributeMaxDynamicSharedMemorySize, 197632);

    k_gram<<<16, 256, 66048>>>(W);
    k_proj<<<dim3(SB * SS / 128, 2), 256, 131072>>>(xq, xv, W);
    k_chunksum<<<dim3(NCH, SB), 128>>>(xk);
    k_su<<<dim3(NCH, SB), 256, 198144>>>(xk);
    k_prefix_mat<<<SB * SD * SD / 256, 256>>>();
    k_out<<<dim3(NCH, SB), 256, 197632>>>(xk, out);
}